// round 2
// baseline (speedup 1.0000x reference)
#include <cuda_runtime.h>
#include <math.h>

#define S_LEN  2048
#define B_SZ   2
#define DMODEL 4096
#define KVDIM  1024
#define HD     128
#define NH     32
#define NKV    8

// ---------------- scratch (static device globals; no allocation) ----------------
__device__ float g_q[(size_t)B_SZ * NH  * S_LEN * HD];   // [b][h][s][d]
__device__ float g_k[(size_t)B_SZ * NKV * S_LEN * HD];   // [b][g][s][d]
__device__ float g_v[(size_t)B_SZ * NKV * S_LEN * HD];   // [b][g][s][d]
__device__ float g_attn[(size_t)B_SZ * S_LEN * DMODEL];  // [b*s][h*128+d]

// ---------------- GEMM: 128x128 tile, K-step 16, 256 threads, 8x8/thread -------
// mode 1: A = x, fused QKV (W0=wq, W1=wk, W2=wv), scatter epilogue into g_q/g_k/g_v
// mode 2: A = g_attn (internal), C = A @ W0 plain row-major store
__global__ __launch_bounds__(256) void gemm_kernel(
    const float* __restrict__ A_in, int K, int mode,
    const float* __restrict__ W0, const float* __restrict__ W1,
    const float* __restrict__ W2, float* __restrict__ C, int ldc)
{
    __shared__ float As[16][132];   // transposed A tile: As[k][m]
    __shared__ float Bs[16][132];   // Bs[k][n]

    const float* A = (mode == 2) ? g_attn : A_in;

    const int t  = threadIdx.x;
    const int m0 = blockIdx.y * 128;
    const int n0 = blockIdx.x * 128;

    const float* Bp; int ldb; int bc;
    if (mode == 2)                  { Bp = W0; ldb = ldc;   bc = n0; }
    else if (n0 < DMODEL)           { Bp = W0; ldb = DMODEL; bc = n0; }
    else if (n0 < DMODEL + KVDIM)   { Bp = W1; ldb = KVDIM;  bc = n0 - DMODEL; }
    else                            { Bp = W2; ldb = KVDIM;  bc = n0 - DMODEL - KVDIM; }

    const int arow = t >> 2;           // 0..63
    const int acol = (t & 3) << 2;     // 0,4,8,12
    const int brow = t >> 5;           // 0..7
    const int bcol = (t & 31) << 2;    // 0..124

    const float* Ap  = A  + (size_t)(m0 + arow) * K + acol;
    const float* Bpp = Bp + (size_t)brow * ldb + bc + bcol;

    const int ty = t >> 4, tx = t & 15;
    float acc[8][8];
#pragma unroll
    for (int i = 0; i < 8; i++)
#pragma unroll
        for (int j = 0; j < 8; j++) acc[i][j] = 0.f;

    for (int k0 = 0; k0 < K; k0 += 16) {
        float4 a0 = *(const float4*)Ap;
        float4 a1 = *(const float4*)(Ap + (size_t)64 * K);
        float4 b0 = *(const float4*)Bpp;
        float4 b1 = *(const float4*)(Bpp + (size_t)8 * ldb);

        As[acol + 0][arow] = a0.x;  As[acol + 1][arow] = a0.y;
        As[acol + 2][arow] = a0.z;  As[acol + 3][arow] = a0.w;
        As[acol + 0][arow + 64] = a1.x;  As[acol + 1][arow + 64] = a1.y;
        As[acol + 2][arow + 64] = a1.z;  As[acol + 3][arow + 64] = a1.w;
        *(float4*)&Bs[brow][bcol]     = b0;
        *(float4*)&Bs[brow + 8][bcol] = b1;
        __syncthreads();

#pragma unroll
        for (int kk = 0; kk < 16; kk++) {
            float ar[8], br[8];
            *(float4*)&ar[0] = *(const float4*)&As[kk][ty * 8];
            *(float4*)&ar[4] = *(const float4*)&As[kk][ty * 8 + 4];
            *(float4*)&br[0] = *(const float4*)&Bs[kk][tx * 8];
            *(float4*)&br[4] = *(const float4*)&Bs[kk][tx * 8 + 4];
#pragma unroll
            for (int i = 0; i < 8; i++)
#pragma unroll
                for (int j = 0; j < 8; j++)
                    acc[i][j] = fmaf(ar[i], br[j], acc[i][j]);
        }
        __syncthreads();
        Ap  += 16;
        Bpp += (size_t)16 * ldb;
    }

    if (mode == 2) {
#pragma unroll
        for (int i = 0; i < 8; i++) {
            float* cp = C + (size_t)(m0 + ty * 8 + i) * ldc + n0 + tx * 8;
            *(float4*)cp       = make_float4(acc[i][0], acc[i][1], acc[i][2], acc[i][3]);
            *(float4*)(cp + 4) = make_float4(acc[i][4], acc[i][5], acc[i][6], acc[i][7]);
        }
    } else {
        // each 128-wide n-block is exactly one head; each 128-tall m-block stays in one batch
        const int b    = m0 >> 11;        // m0 / 2048
        const int srow = m0 & (S_LEN - 1);
        float* dst;
        if (n0 < DMODEL)
            dst = g_q + ((size_t)(b * NH  + (n0 >> 7)) * S_LEN + srow) * HD;
        else if (n0 < DMODEL + KVDIM)
            dst = g_k + ((size_t)(b * NKV + ((n0 - DMODEL) >> 7)) * S_LEN + srow) * HD;
        else
            dst = g_v + ((size_t)(b * NKV + ((n0 - DMODEL - KVDIM) >> 7)) * S_LEN + srow) * HD;
#pragma unroll
        for (int i = 0; i < 8; i++) {
            float* cp = dst + (size_t)(ty * 8 + i) * HD + tx * 8;
            *(float4*)cp       = make_float4(acc[i][0], acc[i][1], acc[i][2], acc[i][3]);
            *(float4*)(cp + 4) = make_float4(acc[i][4], acc[i][5], acc[i][6], acc[i][7]);
        }
    }
}

// ---------------- RoPE (in-place on g_q / g_k) ----------------------------------
__global__ void rope_kernel(int which, int total,
                            const float* __restrict__ cs, const float* __restrict__ sn)
{
    int idx = blockIdx.x * blockDim.x + threadIdx.x;
    if (idx >= total) return;
    float* xp = which ? g_k : g_q;
    int j = idx & 63;
    int s = (idx >> 6) & (S_LEN - 1);
    float c  = cs[s * 64 + j];
    float si = sn[s * 64 + j];
    float2 v = *(float2*)(xp + (size_t)idx * 2);
    float2 o;
    o.x = v.x * c - v.y * si;
    o.y = v.x * si + v.y * c;
    *(float2*)(xp + (size_t)idx * 2) = o;
}

// ---------------- flash attention: BQ=64, BK=64, full (non-causal) softmax ------
// grid: (S/64, B*NH), 256 threads. smem: Qt[128][68] + KV(max 128*68) + P[64][68]
#define ATTN_SMEM ((128 * 68 + 128 * 68 + 64 * 68) * 4)

__global__ __launch_bounds__(256) void attn_kernel()
{
    extern __shared__ float sm[];
    float* sQ  = sm;                 // Q transposed: sQ[d*68 + r], pre-scaled
    float* sKV = sm + 128 * 68;      // K transposed (d*68+c) then V natural (kk*128+d)
    float* sP  = sm + 2 * 128 * 68;  // probs: sP[r*68 + c]

    const int t  = threadIdx.x;
    const int qt = blockIdx.x;       // q tile 0..31
    const int bh = blockIdx.y;       // 0..63
    const int b  = bh >> 5;
    const int h  = bh & 31;
    const int g  = h >> 2;           // kv head

    const float* qbase = g_q + ((size_t)bh * S_LEN + qt * 64) * HD;
    const float* kbase = g_k + (size_t)(b * NKV + g) * S_LEN * HD;
    const float* vbase = g_v + (size_t)(b * NKV + g) * S_LEN * HD;

    const float scale = 0.08838834764831845f;  // 1/sqrt(128)

    // load Q tile transposed, folded scale
#pragma unroll
    for (int i = 0; i < 32; i++) {
        int idx = t + i * 256;               // 0..8191
        sQ[(idx & 127) * 68 + (idx >> 7)] = qbase[idx] * scale;
    }

    const int ty = t >> 4, tx = t & 15;
    const int r0 = ty * 4, c0 = tx * 4, oc0 = tx * 8;

    float m_i[4], l_i[4], o[4][8];
#pragma unroll
    for (int i = 0; i < 4; i++) {
        m_i[i] = -1e30f; l_i[i] = 0.f;
#pragma unroll
        for (int j = 0; j < 8; j++) o[i][j] = 0.f;
    }

    for (int kt = 0; kt < S_LEN / 64; kt++) {
        __syncthreads();  // prev PV done (and Q ready on iter 0)

        // load K tile transposed
        const float* kp = kbase + (size_t)kt * 64 * HD;
#pragma unroll
        for (int i = 0; i < 32; i++) {
            int idx = t + i * 256;
            sKV[(idx & 127) * 68 + (idx >> 7)] = kp[idx];
        }
        __syncthreads();

        // S = Q K^T (4x4 per thread)
        float s[4][4];
#pragma unroll
        for (int i = 0; i < 4; i++)
#pragma unroll
            for (int j = 0; j < 4; j++) s[i][j] = 0.f;

#pragma unroll 8
        for (int d = 0; d < 128; d++) {
            float4 a  = *(const float4*)&sQ [d * 68 + r0];
            float4 bb = *(const float4*)&sKV[d * 68 + c0];
            float av[4] = {a.x, a.y, a.z, a.w};
            float bv[4] = {bb.x, bb.y, bb.z, bb.w};
#pragma unroll
            for (int i = 0; i < 4; i++)
#pragma unroll
                for (int j = 0; j < 4; j++)
                    s[i][j] = fmaf(av[i], bv[j], s[i][j]);
        }

        // online softmax (rows shared by the 16 tx lanes -> shfl reduce)
        float alpha[4];
#pragma unroll
        for (int i = 0; i < 4; i++) {
            float mx = fmaxf(fmaxf(s[i][0], s[i][1]), fmaxf(s[i][2], s[i][3]));
#pragma unroll
            for (int off = 8; off > 0; off >>= 1)
                mx = fmaxf(mx, __shfl_xor_sync(0xffffffffu, mx, off));
            float mnew = fmaxf(m_i[i], mx);
            float al   = __expf(m_i[i] - mnew);
            m_i[i] = mnew;
            float sum = 0.f;
#pragma unroll
            for (int j = 0; j < 4; j++) { s[i][j] = __expf(s[i][j] - mnew); sum += s[i][j]; }
#pragma unroll
            for (int off = 8; off > 0; off >>= 1)
                sum += __shfl_xor_sync(0xffffffffu, sum, off);
            l_i[i] = l_i[i] * al + sum;
            alpha[i] = al;
        }

        // stash probs
#pragma unroll
        for (int i = 0; i < 4; i++)
#pragma unroll
            for (int j = 0; j < 4; j++)
                sP[(r0 + i) * 68 + c0 + j] = s[i][j];
        __syncthreads();  // done reading K-tile + all P written

        // load V tile (natural layout) into same buffer
        const float* vp = vbase + (size_t)kt * 64 * HD;
#pragma unroll
        for (int i = 0; i < 32; i++) {
            int idx = t + i * 256;
            sKV[idx] = vp[idx];
        }
        __syncthreads();

        // rescale + O += P V
#pragma unroll
        for (int i = 0; i < 4; i++) {
            float al = alpha[i];
#pragma unroll
            for (int j = 0; j < 8; j++) o[i][j] *= al;
        }
#pragma unroll 4
        for (int kk = 0; kk < 64; kk++) {
            float4 v0 = *(const float4*)&sKV[kk * 128 + oc0];
            float4 v1 = *(const float4*)&sKV[kk * 128 + oc0 + 4];
            float vv[8] = {v0.x, v0.y, v0.z, v0.w, v1.x, v1.y, v1.z, v1.w};
#pragma unroll
            for (int i = 0; i < 4; i++) {
                float p = sP[(r0 + i) * 68 + kk];
#pragma unroll
                for (int j = 0; j < 8; j++)
                    o[i][j] = fmaf(p, vv[j], o[i][j]);
            }
        }
    }

    // normalize + write to g_attn [b*s][h*128+d]
#pragma unroll
    for (int i = 0; i < 4; i++) {
        float inv = 1.f / l_i[i];
        int srow  = qt * 64 + r0 + i;
        float* op = g_attn + ((size_t)(b * S_LEN + srow)) * DMODEL + h * HD + oc0;
        *(float4*)op       = make_float4(o[i][0] * inv, o[i][1] * inv, o[i][2] * inv, o[i][3] * inv);
        *(float4*)(op + 4) = make_float4(o[i][4] * inv, o[i][5] * inv, o[i][6] * inv, o[i][7] * inv);
    }
}

// ---------------- launch ---------------------------------------------------------
extern "C" void kernel_launch(void* const* d_in, const int* in_sizes, int n_in,
                              void* d_out, int out_size)
{
    const float* x  = (const float*)d_in[0];
    const float* cs = (const float*)d_in[1];
    const float* sn = (const float*)d_in[2];
    const float* wq = (const float*)d_in[3];
    const float* wk = (const float*)d_in[4];
    const float* wv = (const float*)d_in[5];
    const float* wo = (const float*)d_in[6];
    // d_in[7] = start_pos (always 0 for this problem)
    float* out = (float*)d_out;

    cudaFuncSetAttribute(attn_kernel, cudaFuncAttributeMaxDynamicSharedMemorySize, ATTN_SMEM);

    // 1) fused QKV projection + scatter to [b][h][s][d] scratch
    gemm_kernel<<<dim3((DMODEL + 2 * KVDIM) / 128, (B_SZ * S_LEN) / 128), 256>>>(
        x, DMODEL, 1, wq, wk, wv, nullptr, 0);

    // 2) RoPE on Q and K
    rope_kernel<<<(B_SZ * NH * S_LEN * 64) / 256, 256>>>(0, B_SZ * NH * S_LEN * 64, cs, sn);
    rope_kernel<<<(B_SZ * NKV * S_LEN * 64) / 256, 256>>>(1, B_SZ * NKV * S_LEN * 64, cs, sn);

    // 3) attention
    attn_kernel<<<dim3(S_LEN / 64, B_SZ * NH), 256, ATTN_SMEM>>>();

    // 4) output projection (A = g_attn picked up inside the kernel)
    gemm_kernel<<<dim3(DMODEL / 128, (B_SZ * S_LEN) / 128), 256>>>(
        nullptr, DMODEL, 2, wo, nullptr, nullptr, out, DMODEL);
}